// round 17
// baseline (speedup 1.0000x reference)
#include <cuda_runtime.h>
#include <cuda_fp16.h>
#include <cstdint>
#include <math.h>

#define BB 65536
#define FDIM 267
#define HDIM 256
#define LDIM 64
#define KCODE 1024

// plane strides (u32 per K-pair), K padded to 32-pair (64-elem) chunk multiples
#define KU1 288   // fc1: K=534 -> 9 chunks (fp32 A path)
#define KU2 128   // K=256 -> 4 chunks
#define KU4 192   // fc4: K=331 -> 6 chunks (fp32 A path)

// ---------------- scratch (device globals): separate hi/lo planes ----------------
__device__ uint32_t g_h1h[BB * KU2], g_h1l[BB * KU2];
__device__ uint32_t g_h2h[BB * KU2], g_h2l[BB * KU2];
__device__ float g_q[BB * LDIM];
__device__ float g_esq[KCODE];
__device__ int   g_counts[KCODE];
__device__ float g_partials[512];
__device__ uint32_t g_eth[KCODE * 32], g_etl[KCODE * 32];
__device__ uint32_t g_w1h[256 * KU1], g_w1l[256 * KU1];
__device__ uint32_t g_w2h[256 * KU2], g_w2l[256 * KU2];
__device__ uint32_t g_w3h[256 * KU2], g_w3l[256 * KU2];
__device__ uint32_t g_wmh[128 * KU2], g_wml[128 * KU2];
__device__ uint32_t g_w4h[256 * KU4], g_w4l[256 * KU4];
__device__ uint32_t g_w5h[256 * KU2], g_w5l[256 * KU2];
__device__ uint32_t g_w6h[256 * KU2], g_w6l[256 * KU2];
__device__ uint32_t g_woh[384 * KU2], g_wol[384 * KU2];

// ---------------- helpers ----------------
__device__ __forceinline__ float hi32(float a) {
    return __uint_as_float(__float_as_uint(a) & 0xFFFFE000u);
}
__device__ __forceinline__ uint32_t packh(float x, float y) {
    uint32_t d;
    asm("cvt.rn.f16x2.f32 %0, %1, %2;" : "=r"(d) : "f"(y), "f"(x));
    return d;
}
__device__ __forceinline__ uint32_t split_pack(float a, float b, uint32_t& lo) {
    float ha = hi32(a), hb = hi32(b);
    lo = packh(a - ha, b - hb);
    return packh(ha, hb);
}
__device__ __forceinline__ uint32_t smem_u32(const void* p) {
    uint32_t a;
    asm("{ .reg .u64 t; cvta.to.shared.u64 t, %1; cvt.u32.u64 %0, t; }" : "=r"(a) : "l"(p));
    return a;
}
__device__ __forceinline__ void ldm_x4(uint32_t* d, uint32_t a) {
    asm volatile("ldmatrix.sync.aligned.m8n8.x4.shared.b16 {%0,%1,%2,%3}, [%4];"
        : "=r"(d[0]), "=r"(d[1]), "=r"(d[2]), "=r"(d[3]) : "r"(a));
}
__device__ __forceinline__ void mma16(float* d, const uint32_t* a, const uint32_t* b) {
    asm volatile(
        "mma.sync.aligned.m16n8k16.row.col.f32.f16.f16.f32 "
        "{%0,%1,%2,%3},{%4,%5,%6,%7},{%8,%9},{%0,%1,%2,%3};"
        : "+f"(d[0]), "+f"(d[1]), "+f"(d[2]), "+f"(d[3])
        : "r"(a[0]), "r"(a[1]), "r"(a[2]), "r"(a[3]), "r"(b[0]), "r"(b[1]));
}
__device__ __forceinline__ void sts64(uint32_t* p, uint32_t x, uint32_t y) {
    *(uint2*)p = make_uint2(x, y);
}
__device__ __forceinline__ void cpa16(uint32_t sa, const void* g) {
    asm volatile("cp.async.cg.shared.global [%0], [%1], 16;" :: "r"(sa), "l"(g) : "memory");
}
#define CPA_COMMIT() asm volatile("cp.async.commit_group;" ::: "memory")
#define CPA_WAIT0()  asm volatile("cp.async.wait_group 0;" ::: "memory")

// ---------------- fp16x3 HMMA GEMM ----------------
// 128x128 CTA tile, BK=64, 16 warps (4m x 4n), warp tile 32x32.
// PAIRS_A=true : A from hi/lo planes via cp.async. false: A fp32 concat, reg split.
// B always hi/lo planes via cp.async.
// smem u32 per buf: Ahi[128][36] | Alo | Bhi | Blo = 18432; 2 bufs = 147456 B.
template <bool PAIRS_A>
__global__ void __launch_bounds__(512, 1) mma_gemm(
    const float* __restrict__ A0, int W0,
    const float* __restrict__ A1, int W1,
    const uint32_t* __restrict__ Aph, const uint32_t* __restrict__ Apl, int KUa,
    const uint32_t* __restrict__ Wth, const uint32_t* __restrict__ Wtl, int KUb,
    const float* __restrict__ bias,
    float* __restrict__ Cf, uint32_t* __restrict__ Cph, uint32_t* __restrict__ Cpl, int NUp,
    int N, int K, int relu)
{
    extern __shared__ uint32_t smu[];

    const int tid = threadIdx.x, lane = tid & 31, wid = tid >> 5;
    const int m0 = blockIdx.y * 128, bn = blockIdx.x * 128;
    const int wm0 = (wid >> 2) * 32, wn0 = (wid & 3) * 32;
    const int r = lane >> 2, kq = lane & 3;
    const int NC = (K + 63) >> 6;
    const int prow = tid >> 4, pj = tid & 15;   // fp32-A store mapping
    const int seg = tid & 7, rh = tid >> 3;     // cp.async mapping: 64 row-groups x 8 segs

    const uint32_t sbase = smem_u32(smu);
    const int g = lane >> 3, lr = lane & 7;
    uint32_t aA[2], aB[2];
    #pragma unroll
    for (int mt = 0; mt < 2; mt++) {
        const uint32_t row = wm0 + mt * 16 + (g & 1) * 8 + lr;
        aA[mt] = sbase + 4u * (row * 36 + (g >> 1) * 4);
    }
    #pragma unroll
    for (int np = 0; np < 2; np++) {
        const uint32_t n = wn0 + (2 * np + (g >> 1)) * 8 + lr;
        aB[np] = sbase + 4u * (9216 + n * 36 + (g & 1) * 4);
    }

    float acc[2][4][4];
    #pragma unroll
    for (int i = 0; i < 2; i++)
        #pragma unroll
        for (int j = 0; j < 4; j++)
            #pragma unroll
            for (int e = 0; e < 4; e++) acc[i][j][e] = 0.f;

    float4 a4[4];

    // ---- loaders ----
    auto cpB = [&](int c) {   // B planes, 4 cp.async/thread
        const uint32_t buf = (uint32_t)(c & 1) * 73728u;
        const size_t go = (size_t)c * 32 + seg * 4;
        #pragma unroll
        for (int p = 0; p < 2; p++) {
            const int row = rh + p * 64;
            const uint32_t d = sbase + buf + 4u * (row * 36 + seg * 4);
            cpa16(d + 36864u, Wth + (size_t)(bn + row) * KUb + go);
            cpa16(d + 55296u, Wtl + (size_t)(bn + row) * KUb + go);
        }
    };
    auto cpA = [&](int c) {   // A planes (pairs path), 4 cp.async/thread
        const uint32_t buf = (uint32_t)(c & 1) * 73728u;
        const size_t go = (size_t)c * 32 + seg * 4;
        #pragma unroll
        for (int p = 0; p < 2; p++) {
            const int row = rh + p * 64;
            const uint32_t d = sbase + buf + 4u * (row * 36 + seg * 4);
            cpa16(d,          Aph + (size_t)(m0 + row) * KUa + go);
            cpa16(d + 18432u, Apl + (size_t)(m0 + row) * KUa + go);
        }
    };
    auto pfA = [&](int c) {   // fp32-A prefetch (guarded concat)
        const int kg0 = c * 64 + 4 * pj;
        #pragma unroll
        for (int p = 0; p < 4; p++) {
            const int row = p * 32 + prow;
            float v[4];
            #pragma unroll
            for (int e = 0; e < 4; e++) {
                const int kg = kg0 + e;
                float t = 0.f;
                if (kg < K)
                    t = (kg < W0) ? A0[(size_t)(m0 + row) * W0 + kg]
                                  : A1[(size_t)(m0 + row) * W1 + (kg - W0)];
                v[e] = t;
            }
            a4[p] = make_float4(v[0], v[1], v[2], v[3]);
        }
    };
    auto stA = [&](int b) {   // fp32-A split + store
        uint32_t* base = smu + b * 18432;
        #pragma unroll
        for (int p = 0; p < 4; p++) {
            const int o = (p * 32 + prow) * 36 + 2 * pj;
            const float h0 = hi32(a4[p].x), h1 = hi32(a4[p].y);
            const float h2 = hi32(a4[p].z), h3 = hi32(a4[p].w);
            sts64(base + o, packh(h0, h1), packh(h2, h3));
            sts64(base + 4608 + o,
                  packh(a4[p].x - h0, a4[p].y - h1),
                  packh(a4[p].z - h2, a4[p].w - h3));
        }
    };
    auto compute = [&]() {
        #pragma unroll
        for (int ks = 0; ks < 4; ks++) {
            const uint32_t ko = ks * 32u;
            uint32_t ah[2][4], al[2][4], bh[4][2], bl[4][2];
            ldm_x4(ah[0], aA[0] + ko);
            ldm_x4(ah[1], aA[1] + ko);
            ldm_x4(al[0], aA[0] + ko + 18432u);
            ldm_x4(al[1], aA[1] + ko + 18432u);
            ldm_x4(&bh[0][0], aB[0] + ko);
            ldm_x4(&bh[2][0], aB[1] + ko);
            ldm_x4(&bl[0][0], aB[0] + ko + 18432u);
            ldm_x4(&bl[2][0], aB[1] + ko + 18432u);
            #pragma unroll
            for (int mt = 0; mt < 2; mt++)
                #pragma unroll
                for (int nt = 0; nt < 4; nt++) {
                    mma16(acc[mt][nt], ah[mt], bh[nt]);
                    mma16(acc[mt][nt], ah[mt], bl[nt]);
                    mma16(acc[mt][nt], al[mt], bh[nt]);
                }
        }
    };

    // ---- pipeline ----
    if (PAIRS_A) {
        cpA(0); cpB(0); CPA_COMMIT();
        CPA_WAIT0(); __syncthreads();
    } else {
        pfA(0); cpB(0); CPA_COMMIT();
        stA(0); CPA_WAIT0(); __syncthreads();
    }
    int32_t dshift = 73728;
    for (int c = 0; c < NC; c++) {
        if (c + 1 < NC) {
            if (PAIRS_A) { cpA(c + 1); cpB(c + 1); CPA_COMMIT(); }
            else         { pfA(c + 1); cpB(c + 1); CPA_COMMIT(); }
        }
        compute();
        if (c + 1 < NC) {
            if (!PAIRS_A) stA((c + 1) & 1);
            CPA_WAIT0();
        }
        __syncthreads();
        if (c + 1 < NC) {
            aA[0] += dshift; aA[1] += dshift;
            aB[0] += dshift; aB[1] += dshift;
            dshift = -dshift;
        }
    }

    // ---- epilogue ----
    const bool evenN = (N & 1) == 0;
    #pragma unroll
    for (int mt = 0; mt < 2; mt++) {
        #pragma unroll
        for (int q = 0; q < 2; q++) {
            const int row = m0 + wm0 + mt * 16 + q * 8 + r;
            #pragma unroll
            for (int nt = 0; nt < 4; nt++) {
                const int n = bn + wn0 + nt * 8 + 2 * kq;
                float v0 = acc[mt][nt][q * 2 + 0];
                float v1 = acc[mt][nt][q * 2 + 1];
                if (n + 1 < N) {
                    float o0 = v0 + bias[n];
                    float o1 = v1 + bias[n + 1];
                    if (relu) { o0 = fmaxf(o0, 0.f); o1 = fmaxf(o1, 0.f); }
                    if (Cph) {
                        uint32_t l; uint32_t h = split_pack(o0, o1, l);
                        Cph[(size_t)row * NUp + (n >> 1)] = h;
                        Cpl[(size_t)row * NUp + (n >> 1)] = l;
                    }
                    if (Cf) {
                        if (evenN) {
                            float2 p; p.x = o0; p.y = o1;
                            *(float2*)&Cf[(size_t)row * N + n] = p;
                        } else {
                            Cf[(size_t)row * N + n] = o0;
                            Cf[(size_t)row * N + n + 1] = o1;
                        }
                    }
                } else if (n < N && Cf) {
                    float o0 = v0 + bias[n];
                    if (relu) o0 = fmaxf(o0, 0.f);
                    Cf[(size_t)row * N + n] = o0;
                }
            }
        }
    }
}

// ---------------- fused VQ: mu-GEMM + argmin + gather + loss ----------------
__global__ void __launch_bounds__(512, 1) vq_mma(const float* __restrict__ embed,
                                                 const float* __restrict__ mu_b)
{
    extern __shared__ uint32_t smv[];
    uint32_t* Mh = smv;
    uint32_t* Ml = smv + 4608;
    uint32_t* Eh = smv + 9216;
    uint32_t* El = smv + 13824;
    float* esq_s = (float*)(smv + 36864);

    __shared__ float sbest[16][2][2][8];
    __shared__ int   sidx[16][2][2][8];
    __shared__ int   rowidx[128];
    __shared__ float wsum[16];

    const int tid = threadIdx.x, lane = tid & 31, wid = tid >> 5;
    const int m0 = blockIdx.x * 128;
    const int wm0 = (wid >> 2) * 32;
    const int wq  = wid & 3;
    const int wn0 = wq * 32;
    const int r = lane >> 2, kq = lane & 3;
    const int seg = tid & 7, rh = tid >> 3;

    const uint32_t sbase = smem_u32(smv);
    const int g = lane >> 3, lr = lane & 7;

    #pragma unroll
    for (int i = tid; i < KCODE; i += 512) esq_s[i] = g_esq[i];

    // ===== phase 1: mu = h1 * Wm^T + mu_b =====
    {
        uint32_t p1A[2], p1B;
        #pragma unroll
        for (int mt = 0; mt < 2; mt++) {
            const uint32_t row = wm0 + mt * 16 + (g & 1) * 8 + lr;
            p1A[mt] = sbase + 36864u + 4u * (row * 36 + (g >> 1) * 4);
        }
        {
            const uint32_t n = wq * 16 + (g >> 1) * 8 + lr;
            p1B = sbase + 110592u + 4u * (n * 36 + (g & 1) * 4);
        }

        float acc1[2][2][4];
        #pragma unroll
        for (int i = 0; i < 2; i++)
            #pragma unroll
            for (int j = 0; j < 2; j++)
                #pragma unroll
                for (int e = 0; e < 4; e++) acc1[i][j][e] = 0.f;

        uint4 ahv[2], alv[2], bhv, blv;
        auto pf1 = [&](int c) {
            const size_t go = (size_t)c * 32 + seg * 4;
            #pragma unroll
            for (int p = 0; p < 2; p++) {
                const int row = rh + p * 64;
                ahv[p] = *(const uint4*)&g_h1h[(size_t)(m0 + row) * KU2 + go];
                alv[p] = *(const uint4*)&g_h1l[(size_t)(m0 + row) * KU2 + go];
            }
            bhv = *(const uint4*)&g_wmh[(size_t)rh * KU2 + go];
            blv = *(const uint4*)&g_wml[(size_t)rh * KU2 + go];
        };
        auto st1 = [&](int b) {
            uint32_t* A = smv + 9216 + b * 9216;
            uint32_t* Bq = smv + 27648 + b * 4608;
            #pragma unroll
            for (int p = 0; p < 2; p++) {
                const int row = rh + p * 64;
                *(uint4*)&A[row * 36 + seg * 4] = ahv[p];
                *(uint4*)&A[4608 + row * 36 + seg * 4] = alv[p];
            }
            *(uint4*)&Bq[rh * 36 + seg * 4] = bhv;        // rh < 64: B tile rows
            *(uint4*)&Bq[2304 + rh * 36 + seg * 4] = blv;
        };
        auto cmp1 = [&](int b) {
            const uint32_t abuf = (uint32_t)b * 36864u;
            const uint32_t bbuf = (uint32_t)b * 18432u;
            #pragma unroll
            for (int ks = 0; ks < 4; ks++) {
                const uint32_t ko = ks * 32u;
                uint32_t ah[2][4], al[2][4], bh[2][2], bl[2][2];
                ldm_x4(ah[0], p1A[0] + abuf + ko);
                ldm_x4(ah[1], p1A[1] + abuf + ko);
                ldm_x4(al[0], p1A[0] + abuf + ko + 18432u);
                ldm_x4(al[1], p1A[1] + abuf + ko + 18432u);
                ldm_x4(&bh[0][0], p1B + bbuf + ko);
                ldm_x4(&bl[0][0], p1B + bbuf + ko + 9216u);
                #pragma unroll
                for (int mt = 0; mt < 2; mt++)
                    #pragma unroll
                    for (int nt = 0; nt < 2; nt++) {
                        mma16(acc1[mt][nt], ah[mt], bh[nt]);
                        mma16(acc1[mt][nt], ah[mt], bl[nt]);
                        mma16(acc1[mt][nt], al[mt], bh[nt]);
                    }
            }
        };

        pf1(0); st1(0); __syncthreads();
        for (int c = 0; c < 4; c++) {
            if (c < 3) pf1(c + 1);
            cmp1(c & 1);
            if (c < 3) st1((c + 1) & 1);
            __syncthreads();
        }

        #pragma unroll
        for (int mt = 0; mt < 2; mt++)
            #pragma unroll
            for (int qq = 0; qq < 2; qq++) {
                const int m = wm0 + mt * 16 + qq * 8 + r;
                #pragma unroll
                for (int nt = 0; nt < 2; nt++) {
                    const int n = wq * 16 + nt * 8 + 2 * kq;
                    const float o0 = acc1[mt][nt][qq * 2 + 0] + mu_b[n];
                    const float o1 = acc1[mt][nt][qq * 2 + 1] + mu_b[n + 1];
                    uint32_t l; uint32_t h = split_pack(o0, o1, l);
                    Mh[m * 36 + (n >> 1)] = h;
                    Ml[m * 36 + (n >> 1)] = l;
                }
            }
    }

    // ===== phase 2: argmin =====
    float best[2][2];
    int   bidx[2][2];
    #pragma unroll
    for (int i = 0; i < 2; i++)
        #pragma unroll
        for (int j = 0; j < 2; j++) { best[i][j] = 3.4e38f; bidx[i][j] = 0; }

    uint32_t aM[2], aE[2];
    #pragma unroll
    for (int mt = 0; mt < 2; mt++) {
        const uint32_t row = wm0 + mt * 16 + (g & 1) * 8 + lr;
        aM[mt] = sbase + 4u * (row * 36 + (g >> 1) * 4);
    }
    #pragma unroll
    for (int np = 0; np < 2; np++) {
        const uint32_t n = wn0 + (2 * np + (g >> 1)) * 8 + lr;
        aE[np] = sbase + 4u * (9216 + n * 36 + (g & 1) * 4);
    }

    uint32_t uh[8], ul[8];
    for (int ct = 0; ct < 8; ct++) {
        #pragma unroll
        for (int ps = 0; ps < 8; ps++) {
            const int row = ps * 16 + wid;
            uh[ps] = g_eth[(size_t)(ct * 128 + row) * 32 + lane];
            ul[ps] = g_etl[(size_t)(ct * 128 + row) * 32 + lane];
        }
        __syncthreads();
        #pragma unroll
        for (int ps = 0; ps < 8; ps++) {
            const int row = ps * 16 + wid;
            Eh[row * 36 + lane] = uh[ps];
            El[row * 36 + lane] = ul[ps];
        }
        __syncthreads();

        float acc[2][4][4];
        #pragma unroll
        for (int i = 0; i < 2; i++)
            #pragma unroll
            for (int j = 0; j < 4; j++)
                #pragma unroll
                for (int e = 0; e < 4; e++) acc[i][j][e] = 0.f;

        #pragma unroll
        for (int ks = 0; ks < 4; ks++) {
            const uint32_t ko = ks * 32u;
            uint32_t ah[2][4], al[2][4], bh[4][2], bl[4][2];
            ldm_x4(ah[0], aM[0] + ko);
            ldm_x4(ah[1], aM[1] + ko);
            ldm_x4(al[0], aM[0] + ko + 18432u);
            ldm_x4(al[1], aM[1] + ko + 18432u);
            ldm_x4(&bh[0][0], aE[0] + ko);
            ldm_x4(&bh[2][0], aE[1] + ko);
            ldm_x4(&bl[0][0], aE[0] + ko + 18432u);
            ldm_x4(&bl[2][0], aE[1] + ko + 18432u);
            #pragma unroll
            for (int mt = 0; mt < 2; mt++)
                #pragma unroll
                for (int nt = 0; nt < 4; nt++) {
                    mma16(acc[mt][nt], ah[mt], bh[nt]);
                    mma16(acc[mt][nt], ah[mt], bl[nt]);
                    mma16(acc[mt][nt], al[mt], bh[nt]);
                }
        }

        #pragma unroll
        for (int mt = 0; mt < 2; mt++)
            #pragma unroll
            for (int q = 0; q < 2; q++)
                #pragma unroll
                for (int nt = 0; nt < 4; nt++)
                    #pragma unroll
                    for (int e = 0; e < 2; e++) {
                        const int code = ct * 128 + wn0 + nt * 8 + 2 * kq + e;
                        const float sc = esq_s[code] - 2.f * acc[mt][nt][q * 2 + e];
                        if (sc < best[mt][q]) { best[mt][q] = sc; bidx[mt][q] = code; }
                    }
        __syncthreads();
    }

    #pragma unroll
    for (int mt = 0; mt < 2; mt++)
        #pragma unroll
        for (int q = 0; q < 2; q++) {
            float b = best[mt][q]; int ix = bidx[mt][q];
            #pragma unroll
            for (int s = 1; s <= 2; s <<= 1) {
                const float ob = __shfl_xor_sync(0xffffffffu, b, s);
                const int   oi = __shfl_xor_sync(0xffffffffu, ix, s);
                if (ob < b || (ob == b && oi < ix)) { b = ob; ix = oi; }
            }
            if (kq == 0) { sbest[wid][mt][q][r] = b; sidx[wid][mt][q][r] = ix; }
        }
    __syncthreads();

    if (wq == 0 && kq == 0) {
        #pragma unroll
        for (int mt = 0; mt < 2; mt++)
            #pragma unroll
            for (int q = 0; q < 2; q++) {
                float b0 = sbest[wid][mt][q][r]; int i0 = sidx[wid][mt][q][r];
                #pragma unroll
                for (int w2 = 1; w2 < 4; w2++) {
                    float b1 = sbest[wid + w2][mt][q][r]; int i1 = sidx[wid + w2][mt][q][r];
                    if (b1 < b0 || (b1 == b0 && i1 < i0)) { b0 = b1; i0 = i1; }
                }
                rowidx[wm0 + mt * 16 + r + q * 8] = i0;
            }
    }
    __syncthreads();

    // ===== phase 3: gather q + loss + histogram =====
    {
        float lsum = 0.f;
        #pragma unroll
        for (int rr = 0; rr < 8; rr++) {
            const int row = wid * 8 + rr;
            const int idx = rowidx[row];
            const float e0 = embed[(size_t)(2 * lane) * KCODE + idx];
            const float e1 = embed[(size_t)(2 * lane + 1) * KCODE + idx];
            float2 qv; qv.x = e0; qv.y = e1;
            *(float2*)&g_q[(size_t)(m0 + row) * LDIM + 2 * lane] = qv;
            const __half2 H = *(const __half2*)&Mh[row * 36 + lane];
            const __half2 L = *(const __half2*)&Ml[row * 36 + lane];
            const float mu0 = __half2float(H.x) + __half2float(L.x);
            const float mu1 = __half2float(H.y) + __half2float(L.y);
            const float d0 = e0 - mu0, d1 = e1 - mu1;
            lsum += d0 * d0 + d1 * d1;
            if (lane == 0) atomicAdd(&g_counts[idx], 1);
        }
        #pragma unroll
        for (int off = 16; off; off >>= 1) lsum += __shfl_down_sync(0xffffffffu, lsum, off);
        if (lane == 0) wsum[wid] = lsum;
        __syncthreads();
        if (tid == 0) {
            float t = 0.f;
            #pragma unroll
            for (int i = 0; i < 16; i++) t += wsum[i];
            g_partials[blockIdx.x] = t;
        }
    }
}

// ---------------- single fused prep kernel (plane outputs) ----------------
__device__ __forceinline__ void wsplit_elem(const float* __restrict__ W,
                                            uint32_t* __restrict__ Wh,
                                            uint32_t* __restrict__ Wl,
                                            int N, int K, int KU, int i)
{
    int n = i / KU, j = i - n * KU;
    int k0 = 2 * j;
    float a = (n < N && k0 < K) ? W[(size_t)n * K + k0] : 0.f;
    float b = (n < N && k0 + 1 < K) ? W[(size_t)n * K + k0 + 1] : 0.f;
    uint32_t l; uint32_t h = split_pack(a, b, l);
    Wh[i] = h; Wl[i] = l;
}

#define PB_W1 0
#define PB_W2 (PB_W1 + (256 * KU1) / 256)
#define PB_W3 (PB_W2 + (256 * KU2) / 256)
#define PB_WM (PB_W3 + (256 * KU2) / 256)
#define PB_W4 (PB_WM + (128 * KU2) / 256)
#define PB_W5 (PB_W4 + (256 * KU4) / 256)
#define PB_W6 (PB_W5 + (256 * KU2) / 256)
#define PB_WO (PB_W6 + (256 * KU2) / 256)
#define PB_ET (PB_WO + (384 * KU2) / 256)
#define PB_ZC (PB_ET + (KCODE * 32) / 256)
#define PB_END (PB_ZC + 4)

__global__ void __launch_bounds__(256) prep_all(
    const float* __restrict__ fc1_w, const float* __restrict__ fc2_w,
    const float* __restrict__ fc3_w, const float* __restrict__ mu_w,
    const float* __restrict__ fc4_w, const float* __restrict__ fc5_w,
    const float* __restrict__ fc6_w, const float* __restrict__ out_w,
    const float* __restrict__ embed)
{
    const int b = blockIdx.x, tid = threadIdx.x;
    if (b < PB_W2)      wsplit_elem(fc1_w, g_w1h, g_w1l, 256, 534, KU1, (b - PB_W1) * 256 + tid);
    else if (b < PB_W3) wsplit_elem(fc2_w, g_w2h, g_w2l, 256, 256, KU2, (b - PB_W2) * 256 + tid);
    else if (b < PB_WM) wsplit_elem(fc3_w, g_w3h, g_w3l, 256, 256, KU2, (b - PB_W3) * 256 + tid);
    else if (b < PB_W4) wsplit_elem(mu_w,  g_wmh, g_wml, 64,  256, KU2, (b - PB_WM) * 256 + tid);
    else if (b < PB_W5) wsplit_elem(fc4_w, g_w4h, g_w4l, 256, 331, KU4, (b - PB_W4) * 256 + tid);
    else if (b < PB_W6) wsplit_elem(fc5_w, g_w5h, g_w5l, 256, 256, KU2, (b - PB_W5) * 256 + tid);
    else if (b < PB_WO) wsplit_elem(fc6_w, g_w6h, g_w6l, 256, 256, KU2, (b - PB_W6) * 256 + tid);
    else if (b < PB_ET) wsplit_elem(out_w, g_woh, g_wol, 267, 256, KU2, (b - PB_WO) * 256 + tid);
    else if (b < PB_ZC) {
        const int i = (b - PB_ET) * 256 + tid;
        const int code = i >> 5, j = i & 31;
        const float a = embed[(size_t)(2 * j) * KCODE + code];
        const float bb = embed[(size_t)(2 * j + 1) * KCODE + code];
        uint32_t l; uint32_t h = split_pack(a, bb, l);
        g_eth[i] = h; g_etl[i] = l;
        float s = a * a + bb * bb;
        #pragma unroll
        for (int off = 16; off; off >>= 1) s += __shfl_down_sync(0xffffffffu, s, off);
        if (j == 0) g_esq[code] = s;
    } else {
        const int i = (b - PB_ZC) * 256 + tid;
        if (i < KCODE) g_counts[i] = 0;
    }
}

__global__ void __launch_bounds__(256) finalize_kernel(float* __restrict__ out) {
    __shared__ float red[256];
    const int t = threadIdx.x;
    float s = 0.f;
    for (int i = t; i < 512; i += 256) s += g_partials[i];
    red[t] = s;
    for (int st = 128; st > 0; st >>= 1) { __syncthreads(); if (t < st) red[t] += red[t + st]; }
    __syncthreads();
    float loss = red[0] / (float)((size_t)BB * LDIM);
    __syncthreads();
    float e = 0.f;
    for (int k = t; k < KCODE; k += 256) {
        float p = (float)g_counts[k] / (float)BB;
        e += p * logf(p + 1e-10f);
    }
    red[t] = e;
    for (int st = 128; st > 0; st >>= 1) { __syncthreads(); if (t < st) red[t] += red[t + st]; }
    __syncthreads();
    if (t == 0) {
        out[(size_t)BB * FDIM] = loss;
        out[(size_t)BB * FDIM + 1] = expf(-red[0]);
    }
}

// ---------------- host launcher ----------------
#define SYM(v, s) cudaGetSymbolAddress((void**)&v, s)

extern "C" void kernel_launch(void* const* d_in, const int* in_sizes, int n_in,
                              void* d_out, int out_size)
{
    const float* x     = (const float*)d_in[0];
    const float* c     = (const float*)d_in[1];
    const float* fc1_w = (const float*)d_in[2];
    const float* fc1_b = (const float*)d_in[3];
    const float* fc2_w = (const float*)d_in[4];
    const float* fc2_b = (const float*)d_in[5];
    const float* fc3_w = (const float*)d_in[6];
    const float* fc3_b = (const float*)d_in[7];
    const float* mu_w  = (const float*)d_in[8];
    const float* mu_b  = (const float*)d_in[9];
    const float* fc4_w = (const float*)d_in[10];
    const float* fc4_b = (const float*)d_in[11];
    const float* fc5_w = (const float*)d_in[12];
    const float* fc5_b = (const float*)d_in[13];
    const float* fc6_w = (const float*)d_in[14];
    const float* fc6_b = (const float*)d_in[15];
    const float* out_w = (const float*)d_in[16];
    const float* out_b = (const float*)d_in[17];
    const float* embed = (const float*)d_in[18];
    float* out = (float*)d_out;

    float *q;
    uint32_t *h1h, *h1l, *h2h, *h2l;
    uint32_t *w1h, *w1l, *w2h, *w2l, *w3h, *w3l, *w4h, *w4l, *w5h, *w5l, *w6h, *w6l, *woh, *wol;
    SYM(q, g_q);
    SYM(h1h, g_h1h); SYM(h1l, g_h1l); SYM(h2h, g_h2h); SYM(h2l, g_h2l);
    SYM(w1h, g_w1h); SYM(w1l, g_w1l); SYM(w2h, g_w2h); SYM(w2l, g_w2l);
    SYM(w3h, g_w3h); SYM(w3l, g_w3l); SYM(w4h, g_w4h); SYM(w4l, g_w4l);
    SYM(w5h, g_w5h); SYM(w5l, g_w5l); SYM(w6h, g_w6h); SYM(w6l, g_w6l);
    SYM(woh, g_woh); SYM(wol, g_wol);

    const int GEMM_SMEM = 2 * 18432 * 4;            // 147456 B
    const int VQ_SMEM   = 37888 * 4;                // 151552 B
    cudaFuncSetAttribute(mma_gemm<false>, cudaFuncAttributeMaxDynamicSharedMemorySize, GEMM_SMEM);
    cudaFuncSetAttribute(mma_gemm<true>,  cudaFuncAttributeMaxDynamicSharedMemorySize, GEMM_SMEM);
    cudaFuncSetAttribute(vq_mma, cudaFuncAttributeMaxDynamicSharedMemorySize, VQ_SMEM);

    const dim3 blk(512);
    const dim3 g256(2, BB / 128);
    const dim3 g267(3, BB / 128);

    prep_all<<<PB_END, 256>>>(fc1_w, fc2_w, fc3_w, mu_w, fc4_w, fc5_w, fc6_w, out_w, embed);

    // encoder
    mma_gemm<false><<<g256, blk, GEMM_SMEM>>>(x, FDIM, c, FDIM, nullptr, nullptr, 0,
                                              w1h, w1l, KU1, fc1_b,
                                              nullptr, h1h, h1l, KU2, HDIM, 534, 1);
    mma_gemm<true><<<g256, blk, GEMM_SMEM>>>(nullptr, 0, nullptr, 0, h1h, h1l, KU2,
                                             w2h, w2l, KU2, fc2_b,
                                             nullptr, h2h, h2l, KU2, HDIM, HDIM, 1);
    mma_gemm<true><<<g256, blk, GEMM_SMEM>>>(nullptr, 0, nullptr, 0, h2h, h2l, KU2,
                                             w3h, w3l, KU2, fc3_b,
                                             nullptr, h1h, h1l, KU2, HDIM, HDIM, 1);

    // fused VQ
    vq_mma<<<BB / 128, 512, VQ_SMEM>>>(embed, mu_b);

    // decoder
    mma_gemm<false><<<g256, blk, GEMM_SMEM>>>(q, LDIM, c, FDIM, nullptr, nullptr, 0,
                                              w4h, w4l, KU4, fc4_b,
                                              nullptr, h2h, h2l, KU2, HDIM, 331, 1);
    mma_gemm<true><<<g256, blk, GEMM_SMEM>>>(nullptr, 0, nullptr, 0, h2h, h2l, KU2,
                                             w5h, w5l, KU2, fc5_b,
                                             nullptr, h1h, h1l, KU2, HDIM, HDIM, 1);
    mma_gemm<true><<<g256, blk, GEMM_SMEM>>>(nullptr, 0, nullptr, 0, h1h, h1l, KU2,
                                             w6h, w6l, KU2, fc6_b,
                                             nullptr, h2h, h2l, KU2, HDIM, HDIM, 1);
    mma_gemm<true><<<g267, blk, GEMM_SMEM>>>(nullptr, 0, nullptr, 0, h2h, h2l, KU2,
                                             woh, wol, KU2, out_b,
                                             out, nullptr, nullptr, 0, FDIM, HDIM, 0);

    // scalars
    finalize_kernel<<<1, 256>>>(out);
}